// round 7
// baseline (speedup 1.0000x reference)
#include <cuda_runtime.h>
#include <math.h>

#define BG 1024
#define PP 128
#define KN 20
#define EPSB 1e-5f

typedef unsigned long long u64;

// ---- persistent scratch ----
__device__ unsigned int g_idx1[BG * PP * 5];   // kNN1 packed neighbor bytes
__device__ unsigned int g_idx2v[BG * PP * 5];  // kNN2 packed neighbor bytes
__device__ float g_x1[BG * PP * 16];           // conv1 output features
__device__ float g_stats[64];                  // sum1/sq1/sum2/sq2

__global__ void k0_zero() { if (threadIdx.x < 64) g_stats[threadIdx.x] = 0.f; }

__device__ __forceinline__ float embed(float d2, int j) {
    return __uint_as_float((__float_as_uint(d2) & 0xFFFFFF80u) | (unsigned)j);
}
__device__ __forceinline__ u64 pk2(float a, float b) {
    u64 r; asm("mov.b64 %0,{%1,%2};" : "=l"(r) : "f"(a), "f"(b)); return r;
}
__device__ __forceinline__ void upk2(float& a, float& b, u64 v) {
    asm("mov.b64 {%0,%1},%2;" : "=f"(a), "=f"(b) : "l"(v));
}
__device__ __forceinline__ u64 fma2(u64 a, u64 b, u64 c) {
    u64 d; asm("fma.rn.f32x2 %0,%1,%2,%3;" : "=l"(d) : "l"(a), "l"(b), "l"(c)); return d;
}
__device__ __forceinline__ u64 add2(u64 a, u64 b) {
    u64 d; asm("add.rn.f32x2 %0,%1,%2;" : "=l"(d) : "l"(a), "l"(b)); return d;
}
__device__ __forceinline__ void ins20(float (&kd)[KN], float dv) {
    kd[KN - 1] = fminf(kd[KN - 1], dv);
#pragma unroll
    for (int p = KN - 1; p > 0; --p) {
        float lo = fminf(kd[p - 1], kd[p]);
        float hi = fmaxf(kd[p - 1], kd[p]);
        kd[p - 1] = lo; kd[p] = hi;
    }
}

// ------------------------------------------------------------------
// K1: kNN on pos (2 parallel lists) + BN1 pre-activation stats
__global__ __launch_bounds__(128) void k1_knn_stats(
    const float* __restrict__ pos,
    const float* __restrict__ w1, const float* __restrict__ b1)
{
    __shared__ float spx[PP], spy[PP], spz[PP], sn[PP];
    __shared__ float v1s[PP * 17];
    __shared__ float w1u[48], w1v[48], b1s[16];
    __shared__ float wpart[4][32];

    int b = blockIdx.x, t = threadIdx.x;
    float px = pos[(b * PP + t) * 3 + 0];
    float py = pos[(b * PP + t) * 3 + 1];
    float pz = pos[(b * PP + t) * 3 + 2];
    spx[t] = px; spy[t] = py; spz[t] = pz;
    if (t < 48) { w1u[t] = w1[t] - w1[t + 48]; w1v[t] = w1[t + 48]; }
    if (t < 16) b1s[t] = b1[t];
    float ni = px * px + py * py + pz * pz;
    sn[t] = ni;
    __syncthreads();

    float kA[KN], kB[KN];
#pragma unroll
    for (int k = 0; k < KN; ++k) { kA[k] = 1e38f; kB[k] = 1e38f; }
#pragma unroll 1
    for (int j = 0; j < PP; j += 2) {
        float da = ni + sn[j]     - 2.f * (px * spx[j]     + py * spy[j]     + pz * spz[j]);
        float db = ni + sn[j + 1] - 2.f * (px * spx[j + 1] + py * spy[j + 1] + pz * spz[j + 1]);
        if (j == t) da = 1e30f;
        if (j + 1 == t) db = 1e30f;
        ins20(kA, embed(da, j));
        ins20(kB, embed(db, j + 1));
    }

    float u1[16];
#pragma unroll
    for (int c = 0; c < 16; ++c) {
        u1[c] = b1s[c] + px * w1u[c] + py * w1u[16 + c] + pz * w1u[32 + c];
        v1s[t * 17 + c] = px * w1v[c] + py * w1v[16 + c] + pz * w1v[32 + c];
    }
    __syncthreads();

    unsigned ji[KN];
#pragma unroll
    for (int i = 0; i < KN; ++i)
        ji[i] = __float_as_uint(fminf(kA[i], kB[KN - 1 - i])) & 127u;
    unsigned* oi = g_idx1 + ((size_t)b * PP + t) * 5;
#pragma unroll
    for (int w = 0; w < 5; ++w)
        oi[w] = ji[4 * w] | (ji[4 * w + 1] << 8) | (ji[4 * w + 2] << 16) | (ji[4 * w + 3] << 24);

    float s[16], q[16];
#pragma unroll
    for (int c = 0; c < 16; ++c) { s[c] = 0.f; q[c] = 0.f; }
#pragma unroll
    for (int k = 0; k < KN; ++k) {
        int j = (int)ji[k];
#pragma unroll
        for (int c = 0; c < 16; ++c) {
            float h = u1[c] + v1s[j * 17 + c];
            s[c] += h; q[c] = fmaf(h, h, q[c]);
        }
    }
#pragma unroll
    for (int c = 0; c < 16; ++c) {
        for (int o = 16; o > 0; o >>= 1) {
            s[c] += __shfl_xor_sync(0xffffffffu, s[c], o);
            q[c] += __shfl_xor_sync(0xffffffffu, q[c], o);
        }
    }
    int lane = t & 31, wid = t >> 5;
    if (lane == 0) {
#pragma unroll
        for (int c = 0; c < 16; ++c) { wpart[wid][c] = s[c]; wpart[wid][16 + c] = q[c]; }
    }
    __syncthreads();
    if (t < 32) {
        float v = wpart[0][t] + wpart[1][t] + wpart[2][t] + wpart[3][t];
        atomicAdd(&g_stats[t], v);
    }
}

// ------------------------------------------------------------------
// K2: h1 = relu(bn1(u+vj)); packed stats of h1@W2+b2
__global__ __launch_bounds__(128) void k2_stats2(
    const float* __restrict__ pos,
    const float* __restrict__ w1, const float* __restrict__ b1,
    const float* __restrict__ g1, const float* __restrict__ be1,
    const float* __restrict__ w2, const float* __restrict__ b2)
{
    __shared__ float v1s[PP * 17];
    __shared__ float w1u[48], w1v[48], b1s[16];
    __shared__ __align__(16) float sw2[256];
    __shared__ __align__(16) float sb2[16];
    __shared__ float bn1s[16], bn1o[16];
    __shared__ float wpart[4][32];

    int b = blockIdx.x, t = threadIdx.x;
    float px = pos[(b * PP + t) * 3 + 0];
    float py = pos[(b * PP + t) * 3 + 1];
    float pz = pos[(b * PP + t) * 3 + 2];
    if (t < 48) { w1u[t] = w1[t] - w1[t + 48]; w1v[t] = w1[t + 48]; }
    if (t < 16) b1s[t] = b1[t];
    sw2[t] = w2[t]; sw2[t + 128] = w2[t + 128];
    if (t < 16) sb2[t] = b2[t];
    if (t >= 32 && t < 48) {
        int c = t - 32;
        const float N = (float)BG * PP * KN;
        float m = g_stats[c] / N;
        float v = g_stats[16 + c] / N - m * m;
        float sc = g1[c] * rsqrtf(v + EPSB);
        bn1s[c] = sc; bn1o[c] = be1[c] - m * sc;
    }
    __syncthreads();

    float u1[16];
#pragma unroll
    for (int c = 0; c < 16; ++c) {
        u1[c] = b1s[c] + px * w1u[c] + py * w1u[16 + c] + pz * w1u[32 + c];
        v1s[t * 17 + c] = px * w1v[c] + py * w1v[16 + c] + pz * w1v[32 + c];
    }
    __syncthreads();

    const unsigned* oi = g_idx1 + ((size_t)b * PP + t) * 5;
    const ulonglong2* sw2u2 = (const ulonglong2*)sw2;
    const u64* sb2u = (const u64*)sb2;

    u64 S[8], Q[8];
#pragma unroll
    for (int g = 0; g < 8; ++g) { S[g] = 0ull; Q[g] = 0ull; }
#pragma unroll 1
    for (int w = 0; w < 5; ++w) {
        unsigned pk = oi[w];
#pragma unroll 1
        for (int kk = 0; kk < 4; ++kk) {
            int j = (int)(pk & 255u); pk >>= 8;
            float h1[16];
#pragma unroll
            for (int c = 0; c < 16; ++c) {
                float pre = u1[c] + v1s[j * 17 + c];
                h1[c] = fmaxf(fmaf(pre, bn1s[c], bn1o[c]), 0.f);
            }
            u64 A2[8];
#pragma unroll
            for (int g = 0; g < 8; ++g) A2[g] = sb2u[g];
#pragma unroll
            for (int f = 0; f < 16; ++f) {
                u64 hv = pk2(h1[f], h1[f]);
                ulonglong2 w0 = sw2u2[f * 4 + 0], w1q = sw2u2[f * 4 + 1];
                ulonglong2 w2q = sw2u2[f * 4 + 2], w3q = sw2u2[f * 4 + 3];
                A2[0] = fma2(hv, w0.x, A2[0]);  A2[1] = fma2(hv, w0.y, A2[1]);
                A2[2] = fma2(hv, w1q.x, A2[2]); A2[3] = fma2(hv, w1q.y, A2[3]);
                A2[4] = fma2(hv, w2q.x, A2[4]); A2[5] = fma2(hv, w2q.y, A2[5]);
                A2[6] = fma2(hv, w3q.x, A2[6]); A2[7] = fma2(hv, w3q.y, A2[7]);
            }
#pragma unroll
            for (int g = 0; g < 8; ++g) {
                S[g] = add2(S[g], A2[g]);
                Q[g] = fma2(A2[g], A2[g], Q[g]);
            }
        }
    }
    float s[16], q[16];
#pragma unroll
    for (int g = 0; g < 8; ++g) {
        upk2(s[2 * g], s[2 * g + 1], S[g]);
        upk2(q[2 * g], q[2 * g + 1], Q[g]);
    }
#pragma unroll
    for (int c = 0; c < 16; ++c) {
        for (int o = 16; o > 0; o >>= 1) {
            s[c] += __shfl_xor_sync(0xffffffffu, s[c], o);
            q[c] += __shfl_xor_sync(0xffffffffu, q[c], o);
        }
    }
    int lane = t & 31, wid = t >> 5;
    if (lane == 0) {
#pragma unroll
        for (int c = 0; c < 16; ++c) { wpart[wid][c] = s[c]; wpart[wid][16 + c] = q[c]; }
    }
    __syncthreads();
    if (t < 32) {
        float v = wpart[0][t] + wpart[1][t] + wpart[2][t] + wpart[3][t];
        atomicAdd(&g_stats[32 + t], v);
    }
}

// ------------------------------------------------------------------
// K3a: conv1 final -> x1 (global) ; kNN2 -> g_idx2v
__global__ __launch_bounds__(128) void k3a_conv1_knn2(
    const float* __restrict__ pos,
    const float* __restrict__ w1, const float* __restrict__ b1,
    const float* __restrict__ g1, const float* __restrict__ be1,
    const float* __restrict__ w2, const float* __restrict__ b2,
    const float* __restrict__ g2, const float* __restrict__ be2,
    const float* __restrict__ w3, const float* __restrict__ b3)
{
    __shared__ __align__(16) float pool[PP * 20];   // v1 rows, then x1 rows
    __shared__ float sn2[PP];
    __shared__ float w1u[48], w1v[48], b1s[16], bn1s[16], bn1o[16];
    __shared__ __align__(16) float sw2[256];
    __shared__ __align__(16) float sw3[256];
    __shared__ __align__(16) float sb2[16];
    __shared__ float sb3[16], bn2s[16], bn2o[16];

    int b = blockIdx.x, t = threadIdx.x;
    float px = pos[(b * PP + t) * 3 + 0];
    float py = pos[(b * PP + t) * 3 + 1];
    float pz = pos[(b * PP + t) * 3 + 2];
    if (t < 48) { w1u[t] = w1[t] - w1[t + 48]; w1v[t] = w1[t + 48]; }
    if (t < 16) { b1s[t] = b1[t]; sb2[t] = b2[t]; sb3[t] = b3[t]; }
    sw2[t] = w2[t]; sw2[t + 128] = w2[t + 128];
    sw3[t] = w3[t]; sw3[t + 128] = w3[t + 128];
    {
        const float N = (float)BG * PP * KN;
        if (t >= 64 && t < 80) {
            int c = t - 64;
            float m = g_stats[c] / N;
            float v = g_stats[16 + c] / N - m * m;
            float sc = g1[c] * rsqrtf(v + EPSB);
            bn1s[c] = sc; bn1o[c] = be1[c] - m * sc;
        } else if (t >= 80 && t < 96) {
            int c = t - 80;
            float m = g_stats[32 + c] / N;
            float v = g_stats[48 + c] / N - m * m;
            float sc = g2[c] * rsqrtf(v + EPSB);
            bn2s[c] = sc; bn2o[c] = be2[c] - m * sc;
        }
    }
    __syncthreads();

    float u1[16];
    {
        float vv[16];
#pragma unroll
        for (int c = 0; c < 16; ++c) {
            u1[c] = b1s[c] + px * w1u[c] + py * w1u[16 + c] + pz * w1u[32 + c];
            vv[c] = px * w1v[c] + py * w1v[16 + c] + pz * w1v[32 + c];
        }
        float4* vr = (float4*)pool + t * 5;
#pragma unroll
        for (int g = 0; g < 4; ++g)
            vr[g] = make_float4(vv[4 * g], vv[4 * g + 1], vv[4 * g + 2], vv[4 * g + 3]);
    }
    __syncthreads();

    const unsigned* oi = g_idx1 + ((size_t)b * PP + t) * 5;
    const ulonglong2* sw2u2 = (const ulonglong2*)sw2;
    const ulonglong2* sw3u2 = (const ulonglong2*)sw3;
    const u64* sb2u = (const u64*)sb2;
    float x1a[16];
#pragma unroll
    for (int c = 0; c < 16; ++c) x1a[c] = -1e30f;
#pragma unroll 1
    for (int w = 0; w < 5; ++w) {
        unsigned pk = oi[w];
#pragma unroll 1
        for (int kk = 0; kk < 4; ++kk) {
            int j = (int)(pk & 255u); pk >>= 8;
            const float4* vp = (const float4*)pool + j * 5;
            float4 q0 = vp[0], q1 = vp[1], q2 = vp[2], q3 = vp[3];
            float h1v[16];
            h1v[0]  = fmaxf(fmaf(u1[0]  + q0.x, bn1s[0],  bn1o[0]),  0.f);
            h1v[1]  = fmaxf(fmaf(u1[1]  + q0.y, bn1s[1],  bn1o[1]),  0.f);
            h1v[2]  = fmaxf(fmaf(u1[2]  + q0.z, bn1s[2],  bn1o[2]),  0.f);
            h1v[3]  = fmaxf(fmaf(u1[3]  + q0.w, bn1s[3],  bn1o[3]),  0.f);
            h1v[4]  = fmaxf(fmaf(u1[4]  + q1.x, bn1s[4],  bn1o[4]),  0.f);
            h1v[5]  = fmaxf(fmaf(u1[5]  + q1.y, bn1s[5],  bn1o[5]),  0.f);
            h1v[6]  = fmaxf(fmaf(u1[6]  + q1.z, bn1s[6],  bn1o[6]),  0.f);
            h1v[7]  = fmaxf(fmaf(u1[7]  + q1.w, bn1s[7],  bn1o[7]),  0.f);
            h1v[8]  = fmaxf(fmaf(u1[8]  + q2.x, bn1s[8],  bn1o[8]),  0.f);
            h1v[9]  = fmaxf(fmaf(u1[9]  + q2.y, bn1s[9],  bn1o[9]),  0.f);
            h1v[10] = fmaxf(fmaf(u1[10] + q2.z, bn1s[10], bn1o[10]), 0.f);
            h1v[11] = fmaxf(fmaf(u1[11] + q2.w, bn1s[11], bn1o[11]), 0.f);
            h1v[12] = fmaxf(fmaf(u1[12] + q3.x, bn1s[12], bn1o[12]), 0.f);
            h1v[13] = fmaxf(fmaf(u1[13] + q3.y, bn1s[13], bn1o[13]), 0.f);
            h1v[14] = fmaxf(fmaf(u1[14] + q3.z, bn1s[14], bn1o[14]), 0.f);
            h1v[15] = fmaxf(fmaf(u1[15] + q3.w, bn1s[15], bn1o[15]), 0.f);

            u64 A2[8];
#pragma unroll
            for (int g = 0; g < 8; ++g) A2[g] = sb2u[g];
#pragma unroll
            for (int f = 0; f < 16; ++f) {
                u64 hv = pk2(h1v[f], h1v[f]);
                ulonglong2 w0 = sw2u2[f * 4 + 0], w1q = sw2u2[f * 4 + 1];
                ulonglong2 w2q = sw2u2[f * 4 + 2], w3q = sw2u2[f * 4 + 3];
                A2[0] = fma2(hv, w0.x, A2[0]);  A2[1] = fma2(hv, w0.y, A2[1]);
                A2[2] = fma2(hv, w1q.x, A2[2]); A2[3] = fma2(hv, w1q.y, A2[3]);
                A2[4] = fma2(hv, w2q.x, A2[4]); A2[5] = fma2(hv, w2q.y, A2[5]);
                A2[6] = fma2(hv, w3q.x, A2[6]); A2[7] = fma2(hv, w3q.y, A2[7]);
            }
            float h2v[16];
#pragma unroll
            for (int g = 0; g < 8; ++g) {
                float a, bb; upk2(a, bb, A2[g]);
                h2v[2 * g]     = fmaxf(fmaf(a,  bn2s[2 * g],     bn2o[2 * g]),     0.f);
                h2v[2 * g + 1] = fmaxf(fmaf(bb, bn2s[2 * g + 1], bn2o[2 * g + 1]), 0.f);
            }
            u64 A3[8];
#pragma unroll
            for (int g = 0; g < 8; ++g) A3[g] = 0ull;
#pragma unroll
            for (int f = 0; f < 16; ++f) {
                u64 hv = pk2(h2v[f], h2v[f]);
                ulonglong2 w0 = sw3u2[f * 4 + 0], w1q = sw3u2[f * 4 + 1];
                ulonglong2 w2q = sw3u2[f * 4 + 2], w3q = sw3u2[f * 4 + 3];
                A3[0] = fma2(hv, w0.x, A3[0]);  A3[1] = fma2(hv, w0.y, A3[1]);
                A3[2] = fma2(hv, w1q.x, A3[2]); A3[3] = fma2(hv, w1q.y, A3[3]);
                A3[4] = fma2(hv, w2q.x, A3[4]); A3[5] = fma2(hv, w2q.y, A3[5]);
                A3[6] = fma2(hv, w3q.x, A3[6]); A3[7] = fma2(hv, w3q.y, A3[7]);
            }
#pragma unroll
            for (int g = 0; g < 8; ++g) {
                float a, bb; upk2(a, bb, A3[g]);
                x1a[2 * g]     = fmaxf(x1a[2 * g],     a);
                x1a[2 * g + 1] = fmaxf(x1a[2 * g + 1], bb);
            }
        }
    }
    float x1f[16];
    float n2 = 0.f;
#pragma unroll
    for (int c = 0; c < 16; ++c) { x1f[c] = x1a[c] + sb3[c]; n2 = fmaf(x1f[c], x1f[c], n2); }
    __syncthreads();   // all v1 reads done
    {
        float4* xr = (float4*)pool + t * 5;
        float4* gx = (float4*)(g_x1 + ((size_t)b * PP + t) * 16);
#pragma unroll
        for (int g = 0; g < 4; ++g) {
            float4 v = make_float4(x1f[4 * g], x1f[4 * g + 1], x1f[4 * g + 2], x1f[4 * g + 3]);
            xr[g] = v; gx[g] = v;
        }
        sn2[t] = n2;
    }
    __syncthreads();

    // kNN2 (2 parallel lists)
    float kA[KN], kB[KN];
#pragma unroll
    for (int k = 0; k < KN; ++k) { kA[k] = 1e38f; kB[k] = 1e38f; }
    const float4* poolq = (const float4*)pool;
#pragma unroll 1
    for (int j = 0; j < PP; j += 2) {
        float4 a0 = poolq[j * 5 + 0], a1 = poolq[j * 5 + 1];
        float4 a2 = poolq[j * 5 + 2], a3 = poolq[j * 5 + 3];
        float4 b0 = poolq[j * 5 + 5], b1q = poolq[j * 5 + 6];
        float4 b2 = poolq[j * 5 + 7], b3 = poolq[j * 5 + 8];
        float dota = x1f[0]*a0.x + x1f[1]*a0.y + x1f[2]*a0.z + x1f[3]*a0.w
                   + x1f[4]*a1.x + x1f[5]*a1.y + x1f[6]*a1.z + x1f[7]*a1.w
                   + x1f[8]*a2.x + x1f[9]*a2.y + x1f[10]*a2.z + x1f[11]*a2.w
                   + x1f[12]*a3.x + x1f[13]*a3.y + x1f[14]*a3.z + x1f[15]*a3.w;
        float dotb = x1f[0]*b0.x + x1f[1]*b0.y + x1f[2]*b0.z + x1f[3]*b0.w
                   + x1f[4]*b1q.x + x1f[5]*b1q.y + x1f[6]*b1q.z + x1f[7]*b1q.w
                   + x1f[8]*b2.x + x1f[9]*b2.y + x1f[10]*b2.z + x1f[11]*b2.w
                   + x1f[12]*b3.x + x1f[13]*b3.y + x1f[14]*b3.z + x1f[15]*b3.w;
        float da = n2 + sn2[j] - 2.f * dota;
        float db = n2 + sn2[j + 1] - 2.f * dotb;
        if (j == t) da = 1e30f;
        if (j + 1 == t) db = 1e30f;
        ins20(kA, embed(da, j));
        ins20(kB, embed(db, j + 1));
    }
    unsigned ji[KN];
#pragma unroll
    for (int i = 0; i < KN; ++i)
        ji[i] = __float_as_uint(fminf(kA[i], kB[KN - 1 - i])) & 127u;
    unsigned* o2 = g_idx2v + ((size_t)b * PP + t) * 5;
#pragma unroll
    for (int w = 0; w < 5; ++w)
        o2[w] = ji[4 * w] | (ji[4 * w + 1] << 8) | (ji[4 * w + 2] << 16) | (ji[4 * w + 3] << 24);
}

// ------------------------------------------------------------------
// K3b: conv2 (group-major, no wide register arrays) ; lin1 ; head
__global__ __launch_bounds__(128) void k3b_conv2_head(
    const float* __restrict__ c2w, const float* __restrict__ c2b,
    const float* __restrict__ lw,  const float* __restrict__ lb,
    const float* __restrict__ mw1, const float* __restrict__ mb1,
    const float* __restrict__ mw2, const float* __restrict__ mb2,
    const float* __restrict__ mw3, const float* __restrict__ mb3,
    float* __restrict__ out)
{
    // pool overlay: phase1 v2s rows stride 36 (0..4608); phase2 lwt[128][48] (0..6144)
    __shared__ __align__(16) float pool[6144];
    __shared__ __align__(16) float c2u[512];
    __shared__ __align__(16) float c2v[512];
    __shared__ __align__(16) float c2bs[32];
    __shared__ float wm[128 * 4];
    __shared__ float gvec[128], h1s[64], h2s[64], outs[2];

    int b = blockIdx.x, t = threadIdx.x;
    int lane = t & 31, wid = t >> 5;
#pragma unroll
    for (int i = t; i < 512; i += 128) { c2u[i] = c2w[i] - c2w[i + 512]; c2v[i] = c2w[i + 512]; }
    if (t < 32) c2bs[t] = c2b[t];

    // own x1 features
    float x1f[16];
    {
        const float4* gx = (const float4*)(g_x1 + ((size_t)b * PP + t) * 16);
#pragma unroll
        for (int g = 0; g < 4; ++g) {
            float4 v = gx[g];
            x1f[4 * g] = v.x; x1f[4 * g + 1] = v.y; x1f[4 * g + 2] = v.z; x1f[4 * g + 3] = v.w;
        }
    }
    __syncthreads();   // c2v/c2u ready; pool free

    // v2 = x1f @ Wv -> smem rows stride 36
    {
        const ulonglong2* cv = (const ulonglong2*)c2v;
        u64 V[16];
#pragma unroll
        for (int g = 0; g < 16; ++g) V[g] = 0ull;
#pragma unroll
        for (int f = 0; f < 16; ++f) {
            u64 hv = pk2(x1f[f], x1f[f]);
#pragma unroll
            for (int g = 0; g < 8; ++g) {
                ulonglong2 wv = cv[f * 8 + g];
                V[2 * g]     = fma2(hv, wv.x, V[2 * g]);
                V[2 * g + 1] = fma2(hv, wv.y, V[2 * g + 1]);
            }
        }
        float4* vr = (float4*)pool + t * 9;
#pragma unroll
        for (int g = 0; g < 8; ++g) {
            float a0, a1v, a2v, a3v;
            upk2(a0, a1v, V[2 * g]); upk2(a2v, a3v, V[2 * g + 1]);
            vr[g] = make_float4(a0, a1v, a2v, a3v);
        }
    }
    __syncthreads();

    // neighbor indices (packed) in regs
    unsigned nw[5];
    {
        const unsigned* o2 = g_idx2v + ((size_t)b * PP + t) * 5;
#pragma unroll
        for (int w = 0; w < 5; ++w) nw[w] = o2[w];
    }

    // build lin1 operand F2 incrementally; conv2 group-major
    u64 F2[24];
#pragma unroll
    for (int g = 0; g < 8; ++g) F2[g] = pk2(x1f[2 * g], x1f[2 * g + 1]);

    const ulonglong2* cu = (const ulonglong2*)c2u;
    const u64* cbu = (const u64*)c2bs;
    const float4* poolq = (const float4*)pool;
#pragma unroll
    for (int grp = 0; grp < 4; ++grp) {
        u64 UG[4];
#pragma unroll
        for (int gg = 0; gg < 4; ++gg) UG[gg] = cbu[grp * 4 + gg];
#pragma unroll
        for (int f = 0; f < 16; ++f) {
            u64 hv = pk2(x1f[f], x1f[f]);
            ulonglong2 w0 = cu[f * 8 + grp * 2 + 0];
            ulonglong2 w1q = cu[f * 8 + grp * 2 + 1];
            UG[0] = fma2(hv, w0.x, UG[0]);  UG[1] = fma2(hv, w0.y, UG[1]);
            UG[2] = fma2(hv, w1q.x, UG[2]); UG[3] = fma2(hv, w1q.y, UG[3]);
        }
        float m[8];
#pragma unroll
        for (int c = 0; c < 8; ++c) m[c] = -1e30f;
#pragma unroll 1
        for (int w = 0; w < 5; ++w) {
            unsigned pk = nw[w];
#pragma unroll 1
            for (int kk = 0; kk < 4; ++kk) {
                int j = (int)(pk & 255u); pk >>= 8;
                float4 v0 = poolq[j * 9 + grp * 2 + 0];
                float4 v1 = poolq[j * 9 + grp * 2 + 1];
                m[0] = fmaxf(m[0], v0.x); m[1] = fmaxf(m[1], v0.y);
                m[2] = fmaxf(m[2], v0.z); m[3] = fmaxf(m[3], v0.w);
                m[4] = fmaxf(m[4], v1.x); m[5] = fmaxf(m[5], v1.y);
                m[6] = fmaxf(m[6], v1.z); m[7] = fmaxf(m[7], v1.w);
            }
        }
#pragma unroll
        for (int gg = 0; gg < 4; ++gg) {
            float a, bb; upk2(a, bb, UG[gg]);
            F2[8 + grp * 4 + gg] = pk2(a + m[2 * gg], bb + m[2 * gg + 1]);
        }
    }
    __syncthreads();   // v2s reads done; pool free for lwt

    // lwt[c][f] = lw[f][c]
#pragma unroll 1
    for (int i = t; i < 48 * 128; i += 128) {
        int c = i / 48, f = i - c * 48;
        pool[i] = lw[f * 128 + c];
    }
    __syncthreads();

    // lin1: per-channel broadcast dot + shuffle/cross-warp max
#pragma unroll 1
    for (int c = 0; c < 128; ++c) {
        const ulonglong2* rw = (const ulonglong2*)(pool + c * 48);
        u64 a0 = 0ull, a1 = 0ull;
#pragma unroll
        for (int g = 0; g < 12; ++g) {
            ulonglong2 wv = rw[g];
            a0 = fma2(F2[2 * g],     wv.x, a0);
            a1 = fma2(F2[2 * g + 1], wv.y, a1);
        }
        float lo, hi; upk2(lo, hi, add2(a0, a1));
        float v = lo + hi;
#pragma unroll
        for (int o = 16; o > 0; o >>= 1)
            v = fmaxf(v, __shfl_xor_sync(0xffffffffu, v, o));
        if (lane == 0) wm[c * 4 + wid] = v;
    }
    __syncthreads();
    gvec[t] = fmaxf(fmaxf(wm[t * 4 + 0], wm[t * 4 + 1]),
                    fmaxf(wm[t * 4 + 2], wm[t * 4 + 3])) + __ldg(lb + t);
    __syncthreads();

    if (t < 64) {
        float a = mb1[t];
#pragma unroll 4
        for (int i = 0; i < 128; ++i) a = fmaf(gvec[i], mw1[i * 64 + t], a);
        h1s[t] = fmaxf(a, 0.f);
    }
    __syncthreads();
    if (t < 64) {
        float a = mb2[t];
#pragma unroll 4
        for (int i = 0; i < 64; ++i) a = fmaf(h1s[i], mw2[i * 64 + t], a);
        h2s[t] = fmaxf(a, 0.f);
    }
    __syncthreads();
    if (t < 2) {
        float a = mb3[t];
#pragma unroll 4
        for (int i = 0; i < 64; ++i) a = fmaf(h2s[i], mw3[i * 2 + t], a);
        outs[t] = a;
    }
    __syncthreads();
    if (t == 0) {
        float o0 = outs[0], o1 = outs[1];
        float m = fmaxf(o0, o1);
        float lse = m + logf(expf(o0 - m) + expf(o1 - m));
        out[b * 2 + 0] = o0 - lse;
        out[b * 2 + 1] = o1 - lse;
    }
}

// ------------------------------------------------------------------
extern "C" void kernel_launch(void* const* d_in, const int* in_sizes, int n_in,
                              void* d_out, int out_size)
{
    (void)in_sizes; (void)n_in; (void)out_size;
    const float* pos   = (const float*)d_in[0];
    const float* c1_w1 = (const float*)d_in[2];
    const float* c1_b1 = (const float*)d_in[3];
    const float* c1_g1 = (const float*)d_in[4];
    const float* c1_be1= (const float*)d_in[5];
    const float* c1_w2 = (const float*)d_in[6];
    const float* c1_b2 = (const float*)d_in[7];
    const float* c1_g2 = (const float*)d_in[8];
    const float* c1_be2= (const float*)d_in[9];
    const float* c1_w3 = (const float*)d_in[10];
    const float* c1_b3 = (const float*)d_in[11];
    const float* c2_w  = (const float*)d_in[12];
    const float* c2_b  = (const float*)d_in[13];
    const float* lw    = (const float*)d_in[14];
    const float* lb    = (const float*)d_in[15];
    const float* m_w1  = (const float*)d_in[16];
    const float* m_b1  = (const float*)d_in[17];
    const float* m_w2  = (const float*)d_in[18];
    const float* m_b2  = (const float*)d_in[19];
    const float* m_w3  = (const float*)d_in[20];
    const float* m_b3  = (const float*)d_in[21];
    float* out = (float*)d_out;

    k0_zero<<<1, 64>>>();
    k1_knn_stats<<<BG, 128>>>(pos, c1_w1, c1_b1);
    k2_stats2<<<BG, 128>>>(pos, c1_w1, c1_b1, c1_g1, c1_be1, c1_w2, c1_b2);
    k3a_conv1_knn2<<<BG, 128>>>(pos,
                                c1_w1, c1_b1, c1_g1, c1_be1,
                                c1_w2, c1_b2, c1_g2, c1_be2,
                                c1_w3, c1_b3);
    k3b_conv2_head<<<BG, 128>>>(c2_w, c2_b, lw, lb,
                                m_w1, m_b1, m_w2, m_b2, m_w3, m_b3,
                                out);
}

// round 8
// speedup vs baseline: 3.3658x; 3.3658x over previous
#include <cuda_runtime.h>
#include <math.h>

#define BG 1024
#define PP 128
#define KN 20
#define EPSB 1e-5f

typedef unsigned long long u64;

// ---- persistent scratch ----
__device__ unsigned int g_idx1[BG * PP * 5];   // 20 packed neighbor bytes per point
__device__ float g_stats[64];                  // sum1/sq1/sum2/sq2

__global__ void k0_zero() { if (threadIdx.x < 64) g_stats[threadIdx.x] = 0.f; }

// embed 7-bit index in mantissa LSBs -> unique keys, register-only top-K
__device__ __forceinline__ float embed(float d2, int j) {
    return __uint_as_float((__float_as_uint(d2) & 0xFFFFFF80u) | (unsigned)j);
}

// packed f32x2 helpers (sm_100+)
__device__ __forceinline__ u64 pk2(float a, float b) {
    u64 r; asm("mov.b64 %0,{%1,%2};" : "=l"(r) : "f"(a), "f"(b)); return r;
}
__device__ __forceinline__ void upk2(float& a, float& b, u64 v) {
    asm("mov.b64 {%0,%1},%2;" : "=f"(a), "=f"(b) : "l"(v));
}
__device__ __forceinline__ u64 fma2(u64 a, u64 b, u64 c) {
    u64 d; asm("fma.rn.f32x2 %0,%1,%2,%3;" : "=l"(d) : "l"(a), "l"(b), "l"(c)); return d;
}
__device__ __forceinline__ u64 add2(u64 a, u64 b) {
    u64 d; asm("add.rn.f32x2 %0,%1,%2;" : "=l"(d) : "l"(a), "l"(b)); return d;
}

// register-only sorted top-20 insert (branch-free bubble network)
__device__ __forceinline__ void ins20(float (&kd)[KN], float dv) {
    kd[KN - 1] = fminf(kd[KN - 1], dv);
#pragma unroll
    for (int p = KN - 1; p > 0; --p) {
        float lo = fminf(kd[p - 1], kd[p]);
        float hi = fmaxf(kd[p - 1], kd[p]);
        kd[p - 1] = lo; kd[p] = hi;
    }
}

// ------------------------------------------------------------------
// K1: kNN on pos (2 parallel lists) + BN1 pre-activation stats
__global__ __launch_bounds__(128) void k1_knn_stats(
    const float* __restrict__ pos,
    const float* __restrict__ w1, const float* __restrict__ b1)
{
    __shared__ float spx[PP], spy[PP], spz[PP], sn[PP];
    __shared__ float v1s[PP * 17];
    __shared__ float w1u[48], w1v[48], b1s[16];
    __shared__ float wpart[4][32];

    int b = blockIdx.x, t = threadIdx.x;
    float px = pos[(b * PP + t) * 3 + 0];
    float py = pos[(b * PP + t) * 3 + 1];
    float pz = pos[(b * PP + t) * 3 + 2];
    spx[t] = px; spy[t] = py; spz[t] = pz;
    if (t < 48) { w1u[t] = w1[t] - w1[t + 48]; w1v[t] = w1[t + 48]; }
    if (t < 16) b1s[t] = b1[t];
    float ni = px * px + py * py + pz * pz;
    sn[t] = ni;
    __syncthreads();

    float kA[KN], kB[KN];
#pragma unroll
    for (int k = 0; k < KN; ++k) { kA[k] = 1e38f; kB[k] = 1e38f; }
#pragma unroll 1
    for (int j = 0; j < PP; j += 2) {
        float da = ni + sn[j]     - 2.f * (px * spx[j]     + py * spy[j]     + pz * spz[j]);
        float db = ni + sn[j + 1] - 2.f * (px * spx[j + 1] + py * spy[j + 1] + pz * spz[j + 1]);
        if (j == t) da = 1e30f;
        if (j + 1 == t) db = 1e30f;
        ins20(kA, embed(da, j));
        ins20(kB, embed(db, j + 1));
    }

    float u1[16];
#pragma unroll
    for (int c = 0; c < 16; ++c) {
        u1[c] = b1s[c] + px * w1u[c] + py * w1u[16 + c] + pz * w1u[32 + c];
        v1s[t * 17 + c] = px * w1v[c] + py * w1v[16 + c] + pz * w1v[32 + c];
    }
    __syncthreads();

    // merge two sorted 20-lists -> set of 20 smallest
    unsigned ji[KN];
#pragma unroll
    for (int i = 0; i < KN; ++i)
        ji[i] = __float_as_uint(fminf(kA[i], kB[KN - 1 - i])) & 127u;
    unsigned* oi = g_idx1 + ((size_t)b * PP + t) * 5;
#pragma unroll
    for (int w = 0; w < 5; ++w)
        oi[w] = ji[4 * w] | (ji[4 * w + 1] << 8) | (ji[4 * w + 2] << 16) | (ji[4 * w + 3] << 24);

    float s[16], q[16];
#pragma unroll
    for (int c = 0; c < 16; ++c) { s[c] = 0.f; q[c] = 0.f; }
#pragma unroll
    for (int k = 0; k < KN; ++k) {
        int j = (int)ji[k];
#pragma unroll
        for (int c = 0; c < 16; ++c) {
            float h = u1[c] + v1s[j * 17 + c];
            s[c] += h; q[c] = fmaf(h, h, q[c]);
        }
    }
#pragma unroll
    for (int c = 0; c < 16; ++c) {
        for (int o = 16; o > 0; o >>= 1) {
            s[c] += __shfl_xor_sync(0xffffffffu, s[c], o);
            q[c] += __shfl_xor_sync(0xffffffffu, q[c], o);
        }
    }
    int lane = t & 31, wid = t >> 5;
    if (lane == 0) {
#pragma unroll
        for (int c = 0; c < 16; ++c) { wpart[wid][c] = s[c]; wpart[wid][16 + c] = q[c]; }
    }
    __syncthreads();
    if (t < 32) {
        float v = wpart[0][t] + wpart[1][t] + wpart[2][t] + wpart[3][t];
        atomicAdd(&g_stats[t], v);
    }
}

// ------------------------------------------------------------------
// K2: h1 = relu(bn1(u+vj)); packed stats of h1@W2+b2
__global__ __launch_bounds__(128) void k2_stats2(
    const float* __restrict__ pos,
    const float* __restrict__ w1, const float* __restrict__ b1,
    const float* __restrict__ g1, const float* __restrict__ be1,
    const float* __restrict__ w2, const float* __restrict__ b2)
{
    __shared__ float v1s[PP * 17];
    __shared__ float w1u[48], w1v[48], b1s[16];
    __shared__ __align__(16) float sw2[256];
    __shared__ __align__(16) float sb2[16];
    __shared__ float bn1s[16], bn1o[16];
    __shared__ float wpart[4][32];

    int b = blockIdx.x, t = threadIdx.x;
    float px = pos[(b * PP + t) * 3 + 0];
    float py = pos[(b * PP + t) * 3 + 1];
    float pz = pos[(b * PP + t) * 3 + 2];
    if (t < 48) { w1u[t] = w1[t] - w1[t + 48]; w1v[t] = w1[t + 48]; }
    if (t < 16) b1s[t] = b1[t];
    sw2[t] = w2[t]; sw2[t + 128] = w2[t + 128];
    if (t < 16) sb2[t] = b2[t];
    if (t >= 32 && t < 48) {
        int c = t - 32;
        const float N = (float)BG * PP * KN;
        float m = g_stats[c] / N;
        float v = g_stats[16 + c] / N - m * m;
        float sc = g1[c] * rsqrtf(v + EPSB);
        bn1s[c] = sc; bn1o[c] = be1[c] - m * sc;
    }
    __syncthreads();

    float u1[16];
#pragma unroll
    for (int c = 0; c < 16; ++c) {
        u1[c] = b1s[c] + px * w1u[c] + py * w1u[16 + c] + pz * w1u[32 + c];
        v1s[t * 17 + c] = px * w1v[c] + py * w1v[16 + c] + pz * w1v[32 + c];
    }
    __syncthreads();

    const unsigned* oi = g_idx1 + ((size_t)b * PP + t) * 5;
    const ulonglong2* sw2u2 = (const ulonglong2*)sw2;
    const u64* sb2u = (const u64*)sb2;

    u64 S[8], Q[8];
#pragma unroll
    for (int g = 0; g < 8; ++g) { S[g] = 0ull; Q[g] = 0ull; }
#pragma unroll 1
    for (int w = 0; w < 5; ++w) {
        unsigned pk = oi[w];
#pragma unroll 1
        for (int kk = 0; kk < 4; ++kk) {
            int j = (int)(pk & 255u); pk >>= 8;
            float h1[16];
#pragma unroll
            for (int c = 0; c < 16; ++c) {
                float pre = u1[c] + v1s[j * 17 + c];
                h1[c] = fmaxf(fmaf(pre, bn1s[c], bn1o[c]), 0.f);
            }
            u64 A2[8];
#pragma unroll
            for (int g = 0; g < 8; ++g) A2[g] = sb2u[g];
#pragma unroll
            for (int f = 0; f < 16; ++f) {
                u64 hv = pk2(h1[f], h1[f]);
                ulonglong2 w0 = sw2u2[f * 4 + 0], w1q = sw2u2[f * 4 + 1];
                ulonglong2 w2q = sw2u2[f * 4 + 2], w3q = sw2u2[f * 4 + 3];
                A2[0] = fma2(hv, w0.x, A2[0]);  A2[1] = fma2(hv, w0.y, A2[1]);
                A2[2] = fma2(hv, w1q.x, A2[2]); A2[3] = fma2(hv, w1q.y, A2[3]);
                A2[4] = fma2(hv, w2q.x, A2[4]); A2[5] = fma2(hv, w2q.y, A2[5]);
                A2[6] = fma2(hv, w3q.x, A2[6]); A2[7] = fma2(hv, w3q.y, A2[7]);
            }
#pragma unroll
            for (int g = 0; g < 8; ++g) {
                S[g] = add2(S[g], A2[g]);
                Q[g] = fma2(A2[g], A2[g], Q[g]);
            }
        }
    }
    float s[16], q[16];
#pragma unroll
    for (int g = 0; g < 8; ++g) {
        upk2(s[2 * g], s[2 * g + 1], S[g]);
        upk2(q[2 * g], q[2 * g + 1], Q[g]);
    }
#pragma unroll
    for (int c = 0; c < 16; ++c) {
        for (int o = 16; o > 0; o >>= 1) {
            s[c] += __shfl_xor_sync(0xffffffffu, s[c], o);
            q[c] += __shfl_xor_sync(0xffffffffu, q[c], o);
        }
    }
    int lane = t & 31, wid = t >> 5;
    if (lane == 0) {
#pragma unroll
        for (int c = 0; c < 16; ++c) { wpart[wid][c] = s[c]; wpart[wid][16 + c] = q[c]; }
    }
    __syncthreads();
    if (t < 32) {
        float v = wpart[0][t] + wpart[1][t] + wpart[2][t] + wpart[3][t];
        atomicAdd(&g_stats[32 + t], v);
    }
}

// ------------------------------------------------------------------
// K3: conv1 final -> x1 ; kNN2 (2-list) ; conv2 (u/v packed) ;
//     lin1 (smem weights + shuffle max) ; head ; log_softmax
// launch_bounds(128, 1): occupancy target 1 CTA/SM -> ptxas free to use
// up to 255 regs and keep ALL per-phase state register-resident (no spill).
__global__ __launch_bounds__(128, 1) void k3_mega(
    const float* __restrict__ pos,
    const float* __restrict__ w1, const float* __restrict__ b1,
    const float* __restrict__ g1, const float* __restrict__ be1,
    const float* __restrict__ w2, const float* __restrict__ b2,
    const float* __restrict__ g2, const float* __restrict__ be2,
    const float* __restrict__ w3, const float* __restrict__ b3,
    const float* __restrict__ c2w, const float* __restrict__ c2b,
    const float* __restrict__ lw,  const float* __restrict__ lb,
    const float* __restrict__ mw1, const float* __restrict__ mb1,
    const float* __restrict__ mw2, const float* __restrict__ mb2,
    const float* __restrict__ mw3, const float* __restrict__ mb3,
    float* __restrict__ out)
{
    // overlay pool:
    //  phase A/B: v1 then x1 rows, stride 20 (0..2560) ; v2s at 2560..6784 (stride 33)
    //  phase D  : lwt[128][48] transposed lin1 weights (0..6144)
    __shared__ __align__(16) float pool[6784];
    __shared__ float sn2[PP];
    __shared__ unsigned char nb2[PP * KN];
    __shared__ float w1u[48], w1v[48], b1s[16], bn1s[16], bn1o[16];
    __shared__ __align__(16) float sw2[256];
    __shared__ __align__(16) float sw3[256];
    __shared__ __align__(16) float sb2[16];
    __shared__ float sb3[16], bn2s[16], bn2o[16];
    __shared__ __align__(16) float c2u[512];
    __shared__ __align__(16) float c2v[512];
    __shared__ __align__(16) float c2bs[32];
    __shared__ float wm[128 * 4];
    __shared__ float gvec[128], h1s[64], h2s[64], outs[2];

    int b = blockIdx.x, t = threadIdx.x;
    int lane = t & 31, wid = t >> 5;
    float px = pos[(b * PP + t) * 3 + 0];
    float py = pos[(b * PP + t) * 3 + 1];
    float pz = pos[(b * PP + t) * 3 + 2];
    if (t < 48) { w1u[t] = w1[t] - w1[t + 48]; w1v[t] = w1[t + 48]; }
    if (t < 16) { b1s[t] = b1[t]; sb2[t] = b2[t]; sb3[t] = b3[t]; }
    sw2[t] = w2[t]; sw2[t + 128] = w2[t + 128];
    sw3[t] = w3[t]; sw3[t + 128] = w3[t + 128];
#pragma unroll
    for (int i = t; i < 512; i += 128) { c2u[i] = c2w[i] - c2w[i + 512]; c2v[i] = c2w[i + 512]; }
    if (t < 32) c2bs[t] = c2b[t];
    {
        const float N = (float)BG * PP * KN;
        if (t >= 64 && t < 80) {
            int c = t - 64;
            float m = g_stats[c] / N;
            float v = g_stats[16 + c] / N - m * m;
            float sc = g1[c] * rsqrtf(v + EPSB);
            bn1s[c] = sc; bn1o[c] = be1[c] - m * sc;
        } else if (t >= 80 && t < 96) {
            int c = t - 80;
            float m = g_stats[32 + c] / N;
            float v = g_stats[48 + c] / N - m * m;
            float sc = g2[c] * rsqrtf(v + EPSB);
            bn2s[c] = sc; bn2o[c] = be2[c] - m * sc;
        }
    }
    __syncthreads();   // all weights/bn consts ready; pool free

    // phase A: u1 (regs) + v1 rows (pool, stride 20, float4 writes)
    float u1[16];
    {
        float vv[16];
#pragma unroll
        for (int c = 0; c < 16; ++c) {
            u1[c] = b1s[c] + px * w1u[c] + py * w1u[16 + c] + pz * w1u[32 + c];
            vv[c] = px * w1v[c] + py * w1v[16 + c] + pz * w1v[32 + c];
        }
        float4* vr = (float4*)pool + t * 5;
#pragma unroll
        for (int g = 0; g < 4; ++g)
            vr[g] = make_float4(vv[4 * g], vv[4 * g + 1], vv[4 * g + 2], vv[4 * g + 3]);
    }
    __syncthreads();

    // ---- conv1 over 20 edges (packed f32x2 layers) ----
    const unsigned* oi = g_idx1 + ((size_t)b * PP + t) * 5;
    const ulonglong2* sw2u2 = (const ulonglong2*)sw2;
    const ulonglong2* sw3u2 = (const ulonglong2*)sw3;
    const u64* sb2u = (const u64*)sb2;
    float x1a[16];
#pragma unroll
    for (int c = 0; c < 16; ++c) x1a[c] = -1e30f;
#pragma unroll 1
    for (int w = 0; w < 5; ++w) {
        unsigned pk = oi[w];
#pragma unroll 1
        for (int kk = 0; kk < 4; ++kk) {
            int j = (int)(pk & 255u); pk >>= 8;
            const float4* vp = (const float4*)pool + j * 5;
            float4 q0 = vp[0], q1 = vp[1], q2 = vp[2], q3 = vp[3];
            float h1v[16];
            h1v[0]  = fmaxf(fmaf(u1[0]  + q0.x, bn1s[0],  bn1o[0]),  0.f);
            h1v[1]  = fmaxf(fmaf(u1[1]  + q0.y, bn1s[1],  bn1o[1]),  0.f);
            h1v[2]  = fmaxf(fmaf(u1[2]  + q0.z, bn1s[2],  bn1o[2]),  0.f);
            h1v[3]  = fmaxf(fmaf(u1[3]  + q0.w, bn1s[3],  bn1o[3]),  0.f);
            h1v[4]  = fmaxf(fmaf(u1[4]  + q1.x, bn1s[4],  bn1o[4]),  0.f);
            h1v[5]  = fmaxf(fmaf(u1[5]  + q1.y, bn1s[5],  bn1o[5]),  0.f);
            h1v[6]  = fmaxf(fmaf(u1[6]  + q1.z, bn1s[6],  bn1o[6]),  0.f);
            h1v[7]  = fmaxf(fmaf(u1[7]  + q1.w, bn1s[7],  bn1o[7]),  0.f);
            h1v[8]  = fmaxf(fmaf(u1[8]  + q2.x, bn1s[8],  bn1o[8]),  0.f);
            h1v[9]  = fmaxf(fmaf(u1[9]  + q2.y, bn1s[9],  bn1o[9]),  0.f);
            h1v[10] = fmaxf(fmaf(u1[10] + q2.z, bn1s[10], bn1o[10]), 0.f);
            h1v[11] = fmaxf(fmaf(u1[11] + q2.w, bn1s[11], bn1o[11]), 0.f);
            h1v[12] = fmaxf(fmaf(u1[12] + q3.x, bn1s[12], bn1o[12]), 0.f);
            h1v[13] = fmaxf(fmaf(u1[13] + q3.y, bn1s[13], bn1o[13]), 0.f);
            h1v[14] = fmaxf(fmaf(u1[14] + q3.z, bn1s[14], bn1o[14]), 0.f);
            h1v[15] = fmaxf(fmaf(u1[15] + q3.w, bn1s[15], bn1o[15]), 0.f);

            u64 A2[8];
#pragma unroll
            for (int g = 0; g < 8; ++g) A2[g] = sb2u[g];
#pragma unroll
            for (int f = 0; f < 16; ++f) {
                u64 hv = pk2(h1v[f], h1v[f]);
                ulonglong2 w0 = sw2u2[f * 4 + 0], w1q = sw2u2[f * 4 + 1];
                ulonglong2 w2q = sw2u2[f * 4 + 2], w3q = sw2u2[f * 4 + 3];
                A2[0] = fma2(hv, w0.x, A2[0]);  A2[1] = fma2(hv, w0.y, A2[1]);
                A2[2] = fma2(hv, w1q.x, A2[2]); A2[3] = fma2(hv, w1q.y, A2[3]);
                A2[4] = fma2(hv, w2q.x, A2[4]); A2[5] = fma2(hv, w2q.y, A2[5]);
                A2[6] = fma2(hv, w3q.x, A2[6]); A2[7] = fma2(hv, w3q.y, A2[7]);
            }
            float h2v[16];
#pragma unroll
            for (int g = 0; g < 8; ++g) {
                float a, bb; upk2(a, bb, A2[g]);
                h2v[2 * g]     = fmaxf(fmaf(a,  bn2s[2 * g],     bn2o[2 * g]),     0.f);
                h2v[2 * g + 1] = fmaxf(fmaf(bb, bn2s[2 * g + 1], bn2o[2 * g + 1]), 0.f);
            }
            u64 A3[8];
#pragma unroll
            for (int g = 0; g < 8; ++g) A3[g] = 0ull;
#pragma unroll
            for (int f = 0; f < 16; ++f) {
                u64 hv = pk2(h2v[f], h2v[f]);
                ulonglong2 w0 = sw3u2[f * 4 + 0], w1q = sw3u2[f * 4 + 1];
                ulonglong2 w2q = sw3u2[f * 4 + 2], w3q = sw3u2[f * 4 + 3];
                A3[0] = fma2(hv, w0.x, A3[0]);  A3[1] = fma2(hv, w0.y, A3[1]);
                A3[2] = fma2(hv, w1q.x, A3[2]); A3[3] = fma2(hv, w1q.y, A3[3]);
                A3[4] = fma2(hv, w2q.x, A3[4]); A3[5] = fma2(hv, w2q.y, A3[5]);
                A3[6] = fma2(hv, w3q.x, A3[6]); A3[7] = fma2(hv, w3q.y, A3[7]);
            }
#pragma unroll
            for (int g = 0; g < 8; ++g) {
                float a, bb; upk2(a, bb, A3[g]);
                x1a[2 * g]     = fmaxf(x1a[2 * g],     a);
                x1a[2 * g + 1] = fmaxf(x1a[2 * g + 1], bb);
            }
        }
    }
    float x1f[16];
    float n2 = 0.f;
#pragma unroll
    for (int c = 0; c < 16; ++c) { x1f[c] = x1a[c] + sb3[c]; n2 = fmaf(x1f[c], x1f[c], n2); }
    __syncthreads();   // all v1 reads done
    {
        float4* xr = (float4*)pool + t * 5;
#pragma unroll
        for (int g = 0; g < 4; ++g)
            xr[g] = make_float4(x1f[4 * g], x1f[4 * g + 1], x1f[4 * g + 2], x1f[4 * g + 3]);
        sn2[t] = n2;
    }
    __syncthreads();

    // ---- kNN2 in 16-d feature space (2 parallel lists) ----
    float kA[KN], kB[KN];
#pragma unroll
    for (int k = 0; k < KN; ++k) { kA[k] = 1e38f; kB[k] = 1e38f; }
    const float4* poolq = (const float4*)pool;
#pragma unroll 1
    for (int j = 0; j < PP; j += 2) {
        float4 a0 = poolq[j * 5 + 0], a1 = poolq[j * 5 + 1];
        float4 a2 = poolq[j * 5 + 2], a3 = poolq[j * 5 + 3];
        float4 b0 = poolq[j * 5 + 5], b1q = poolq[j * 5 + 6];
        float4 b2 = poolq[j * 5 + 7], b3 = poolq[j * 5 + 8];
        float dota = x1f[0]*a0.x + x1f[1]*a0.y + x1f[2]*a0.z + x1f[3]*a0.w
                   + x1f[4]*a1.x + x1f[5]*a1.y + x1f[6]*a1.z + x1f[7]*a1.w
                   + x1f[8]*a2.x + x1f[9]*a2.y + x1f[10]*a2.z + x1f[11]*a2.w
                   + x1f[12]*a3.x + x1f[13]*a3.y + x1f[14]*a3.z + x1f[15]*a3.w;
        float dotb = x1f[0]*b0.x + x1f[1]*b0.y + x1f[2]*b0.z + x1f[3]*b0.w
                   + x1f[4]*b1q.x + x1f[5]*b1q.y + x1f[6]*b1q.z + x1f[7]*b1q.w
                   + x1f[8]*b2.x + x1f[9]*b2.y + x1f[10]*b2.z + x1f[11]*b2.w
                   + x1f[12]*b3.x + x1f[13]*b3.y + x1f[14]*b3.z + x1f[15]*b3.w;
        float da = n2 + sn2[j] - 2.f * dota;
        float db = n2 + sn2[j + 1] - 2.f * dotb;
        if (j == t) da = 1e30f;
        if (j + 1 == t) db = 1e30f;
        ins20(kA, embed(da, j));
        ins20(kB, embed(db, j + 1));
    }
#pragma unroll
    for (int k = 0; k < KN; ++k)
        nb2[t * KN + k] = (unsigned char)(__float_as_uint(fminf(kA[k], kB[KN - 1 - k])) & 127u);

    // ---- conv2: v2 = x1f@Wv -> smem (stride 33); x2 = u2 + max_k v2[j] ----
    float* v2s = pool + 2560;
    {
        const ulonglong2* cv = (const ulonglong2*)c2v;
        u64 V[16];
#pragma unroll
        for (int g = 0; g < 16; ++g) V[g] = 0ull;
#pragma unroll
        for (int f = 0; f < 16; ++f) {
            u64 hv = pk2(x1f[f], x1f[f]);
#pragma unroll
            for (int g = 0; g < 8; ++g) {
                ulonglong2 wv = cv[f * 8 + g];
                V[2 * g]     = fma2(hv, wv.x, V[2 * g]);
                V[2 * g + 1] = fma2(hv, wv.y, V[2 * g + 1]);
            }
        }
#pragma unroll
        for (int g = 0; g < 16; ++g) {
            float a, bb; upk2(a, bb, V[g]);
            v2s[t * 33 + 2 * g] = a; v2s[t * 33 + 2 * g + 1] = bb;
        }
    }
    __syncthreads();

    float x2m[32];
#pragma unroll
    for (int c = 0; c < 32; ++c) x2m[c] = -1e30f;
#pragma unroll 1
    for (int k = 0; k < KN; ++k) {
        int j = (int)nb2[t * KN + k];
#pragma unroll
        for (int c = 0; c < 32; ++c) x2m[c] = fmaxf(x2m[c], v2s[j * 33 + c]);
    }
    float x2a[32];
    {
        const ulonglong2* cu = (const ulonglong2*)c2u;
        const u64* cbu = (const u64*)c2bs;
        u64 U[16];
#pragma unroll
        for (int g = 0; g < 16; ++g) U[g] = cbu[g];
#pragma unroll
        for (int f = 0; f < 16; ++f) {
            u64 hv = pk2(x1f[f], x1f[f]);
#pragma unroll
            for (int g = 0; g < 8; ++g) {
                ulonglong2 wv = cu[f * 8 + g];
                U[2 * g]     = fma2(hv, wv.x, U[2 * g]);
                U[2 * g + 1] = fma2(hv, wv.y, U[2 * g + 1]);
            }
        }
#pragma unroll
        for (int g = 0; g < 16; ++g) {
            float a, bb; upk2(a, bb, U[g]);
            x2a[2 * g]     = a  + x2m[2 * g];
            x2a[2 * g + 1] = bb + x2m[2 * g + 1];
        }
    }
    __syncthreads();   // all v2/x1s reads done; pool free

    // ---- load lin1 weights transposed: lwt[c][f] = lw[f][c] (pool 0..6144) ----
#pragma unroll 1
    for (int i = t; i < 48 * 128; i += 128) {
        int c = i / 48, f = i - c * 48;
        pool[i] = lw[f * 128 + c];
    }
    __syncthreads();

    // ---- lin1: per-channel broadcast dot (packed) + shuffle/cross-warp max ----
    u64 F2[24];
#pragma unroll
    for (int g = 0; g < 8; ++g)  F2[g]     = pk2(x1f[2 * g], x1f[2 * g + 1]);
#pragma unroll
    for (int g = 0; g < 16; ++g) F2[8 + g] = pk2(x2a[2 * g], x2a[2 * g + 1]);
#pragma unroll 1
    for (int c = 0; c < 128; ++c) {
        const ulonglong2* rw = (const ulonglong2*)(pool + c * 48);
        u64 a0 = 0ull, a1 = 0ull;
#pragma unroll
        for (int g = 0; g < 12; ++g) {
            ulonglong2 wv = rw[g];
            a0 = fma2(F2[2 * g],     wv.x, a0);
            a1 = fma2(F2[2 * g + 1], wv.y, a1);
        }
        float lo, hi; upk2(lo, hi, add2(a0, a1));
        float v = lo + hi;
#pragma unroll
        for (int o = 16; o > 0; o >>= 1)
            v = fmaxf(v, __shfl_xor_sync(0xffffffffu, v, o));
        if (lane == 0) wm[c * 4 + wid] = v;
    }
    __syncthreads();
    gvec[t] = fmaxf(fmaxf(wm[t * 4 + 0], wm[t * 4 + 1]),
                    fmaxf(wm[t * 4 + 2], wm[t * 4 + 3])) + __ldg(lb + t);
    __syncthreads();

    // ---- head MLP 128->64->64->2 + log_softmax ----
    if (t < 64) {
        float a = mb1[t];
#pragma unroll 4
        for (int i = 0; i < 128; ++i) a = fmaf(gvec[i], mw1[i * 64 + t], a);
        h1s[t] = fmaxf(a, 0.f);
    }
    __syncthreads();
    if (t < 64) {
        float a = mb2[t];
#pragma unroll 4
        for (int i = 0; i < 64; ++i) a = fmaf(h1s[i], mw2[i * 64 + t], a);
        h2s[t] = fmaxf(a, 0.f);
    }
    __syncthreads();
    if (t < 2) {
        float a = mb3[t];
#pragma unroll 4
        for (int i = 0; i < 64; ++i) a = fmaf(h2s[i], mw3[i * 2 + t], a);
        outs[t] = a;
    }
    __syncthreads();
    if (t == 0) {
        float o0 = outs[0], o1 = outs[1];
        float m = fmaxf(o0, o1);
        float lse = m + logf(expf(o0 - m) + expf(o1 - m));
        out[b * 2 + 0] = o0 - lse;
        out[b * 2 + 1] = o1 - lse;
    }
}

// ------------------------------------------------------------------
extern "C" void kernel_launch(void* const* d_in, const int* in_sizes, int n_in,
                              void* d_out, int out_size)
{
    (void)in_sizes; (void)n_in; (void)out_size;
    const float* pos   = (const float*)d_in[0];
    const float* c1_w1 = (const float*)d_in[2];
    const float* c1_b1 = (const float*)d_in[3];
    const float* c1_g1 = (const float*)d_in[4];
    const float* c1_be1= (const float*)d_in[5];
    const float* c1_w2 = (const float*)d_in[6];
    const float* c1_b2 = (const float*)d_in[7];
    const float* c1_g2 = (const float*)d_in[8];
    const float* c1_be2= (const float*)d_in[9];
    const float* c1_w3 = (const float*)d_in[10];
    const float* c1_b3 = (const float*)d_in[11];
    const float* c2_w  = (const float*)d_in[12];
    const float* c2_b  = (const float*)d_in[13];
    const float* lw    = (const float*)d_in[14];
    const float* lb    = (const float*)d_in[15];
    const float* m_w1  = (const float*)d_in[16];
    const float* m_b1  = (const float*)d_in[17];
    const float* m_w2  = (const float*)d_in[18];
    const float* m_b2  = (const float*)d_in[19];
    const float* m_w3  = (const float*)d_in[20];
    const float* m_b3  = (const float*)d_in[21];
    float* out = (float*)d_out;

    k0_zero<<<1, 64>>>();
    k1_knn_stats<<<BG, 128>>>(pos, c1_w1, c1_b1);
    k2_stats2<<<BG, 128>>>(pos, c1_w1, c1_b1, c1_g1, c1_be1, c1_w2, c1_b2);
    k3_mega<<<BG, 128>>>(pos,
                         c1_w1, c1_b1, c1_g1, c1_be1,
                         c1_w2, c1_b2, c1_g2, c1_be2,
                         c1_w3, c1_b3,
                         c2_w, c2_b, lw, lb,
                         m_w1, m_b1, m_w2, m_b2, m_w3, m_b3,
                         out);
}

// round 9
// speedup vs baseline: 3.4350x; 1.0205x over previous
#include <cuda_runtime.h>
#include <math.h>

#define BG 1024
#define PP 128
#define KN 20
#define EPSB 1e-5f

typedef unsigned long long u64;

// ---- persistent scratch ----
__device__ unsigned int g_idx1[BG * PP * 5];   // 20 packed neighbor bytes per point
__device__ float g_stats[64];                  // sum1/sq1/sum2/sq2

__global__ void k0_zero() { if (threadIdx.x < 64) g_stats[threadIdx.x] = 0.f; }

// embed 7-bit index in mantissa LSBs -> unique keys, register-only top-K
__device__ __forceinline__ float embed(float d2, int j) {
    return __uint_as_float((__float_as_uint(d2) & 0xFFFFFF80u) | (unsigned)j);
}

// packed f32x2 helpers (sm_100+)
__device__ __forceinline__ u64 pk2(float a, float b) {
    u64 r; asm("mov.b64 %0,{%1,%2};" : "=l"(r) : "f"(a), "f"(b)); return r;
}
__device__ __forceinline__ void upk2(float& a, float& b, u64 v) {
    asm("mov.b64 {%0,%1},%2;" : "=f"(a), "=f"(b) : "l"(v));
}
__device__ __forceinline__ u64 fma2(u64 a, u64 b, u64 c) {
    u64 d; asm("fma.rn.f32x2 %0,%1,%2,%3;" : "=l"(d) : "l"(a), "l"(b), "l"(c)); return d;
}
__device__ __forceinline__ u64 add2(u64 a, u64 b) {
    u64 d; asm("add.rn.f32x2 %0,%1,%2;" : "=l"(d) : "l"(a), "l"(b)); return d;
}

// register-only sorted top-20 insert (branch-free bubble network)
__device__ __forceinline__ void ins20(float (&kd)[KN], float dv) {
    kd[KN - 1] = fminf(kd[KN - 1], dv);
#pragma unroll
    for (int p = KN - 1; p > 0; --p) {
        float lo = fminf(kd[p - 1], kd[p]);
        float hi = fmaxf(kd[p - 1], kd[p]);
        kd[p - 1] = lo; kd[p] = hi;
    }
}

// ------------------------------------------------------------------
// K1: kNN on pos (2 lists, 4 candidates/iter = 2 pipelined inserts per list)
//     + BN1 pre-activation stats
__global__ __launch_bounds__(128) void k1_knn_stats(
    const float* __restrict__ pos,
    const float* __restrict__ w1, const float* __restrict__ b1)
{
    __shared__ float spx[PP], spy[PP], spz[PP], sn[PP];
    __shared__ float v1s[PP * 17];
    __shared__ float w1u[48], w1v[48], b1s[16];
    __shared__ float wpart[4][32];

    int b = blockIdx.x, t = threadIdx.x;
    float px = pos[(b * PP + t) * 3 + 0];
    float py = pos[(b * PP + t) * 3 + 1];
    float pz = pos[(b * PP + t) * 3 + 2];
    spx[t] = px; spy[t] = py; spz[t] = pz;
    if (t < 48) { w1u[t] = w1[t] - w1[t + 48]; w1v[t] = w1[t + 48]; }
    if (t < 16) b1s[t] = b1[t];
    float ni = px * px + py * py + pz * pz;
    sn[t] = ni;
    __syncthreads();

    float kA[KN], kB[KN];
#pragma unroll
    for (int k = 0; k < KN; ++k) { kA[k] = 1e38f; kB[k] = 1e38f; }
#pragma unroll 1
    for (int j = 0; j < PP; j += 4) {
        float d0 = ni + sn[j]     - 2.f * (px * spx[j]     + py * spy[j]     + pz * spz[j]);
        float d1 = ni + sn[j + 1] - 2.f * (px * spx[j + 1] + py * spy[j + 1] + pz * spz[j + 1]);
        float d2 = ni + sn[j + 2] - 2.f * (px * spx[j + 2] + py * spy[j + 2] + pz * spz[j + 2]);
        float d3 = ni + sn[j + 3] - 2.f * (px * spx[j + 3] + py * spy[j + 3] + pz * spz[j + 3]);
        if (j == t)     d0 = 1e30f;
        if (j + 1 == t) d1 = 1e30f;
        if (j + 2 == t) d2 = 1e30f;
        if (j + 3 == t) d3 = 1e30f;
        ins20(kA, embed(d0, j));
        ins20(kA, embed(d2, j + 2));
        ins20(kB, embed(d1, j + 1));
        ins20(kB, embed(d3, j + 3));
    }

    float u1[16];
#pragma unroll
    for (int c = 0; c < 16; ++c) {
        u1[c] = b1s[c] + px * w1u[c] + py * w1u[16 + c] + pz * w1u[32 + c];
        v1s[t * 17 + c] = px * w1v[c] + py * w1v[16 + c] + pz * w1v[32 + c];
    }
    __syncthreads();

    // merge two sorted 20-lists -> set of 20 smallest
    unsigned ji[KN];
#pragma unroll
    for (int i = 0; i < KN; ++i)
        ji[i] = __float_as_uint(fminf(kA[i], kB[KN - 1 - i])) & 127u;
    unsigned* oi = g_idx1 + ((size_t)b * PP + t) * 5;
#pragma unroll
    for (int w = 0; w < 5; ++w)
        oi[w] = ji[4 * w] | (ji[4 * w + 1] << 8) | (ji[4 * w + 2] << 16) | (ji[4 * w + 3] << 24);

    float s[16], q[16];
#pragma unroll
    for (int c = 0; c < 16; ++c) { s[c] = 0.f; q[c] = 0.f; }
#pragma unroll
    for (int k = 0; k < KN; ++k) {
        int j = (int)ji[k];
#pragma unroll
        for (int c = 0; c < 16; ++c) {
            float h = u1[c] + v1s[j * 17 + c];
            s[c] += h; q[c] = fmaf(h, h, q[c]);
        }
    }
#pragma unroll
    for (int c = 0; c < 16; ++c) {
        for (int o = 16; o > 0; o >>= 1) {
            s[c] += __shfl_xor_sync(0xffffffffu, s[c], o);
            q[c] += __shfl_xor_sync(0xffffffffu, q[c], o);
        }
    }
    int lane = t & 31, wid = t >> 5;
    if (lane == 0) {
#pragma unroll
        for (int c = 0; c < 16; ++c) { wpart[wid][c] = s[c]; wpart[wid][16 + c] = q[c]; }
    }
    __syncthreads();
    if (t < 32) {
        float v = wpart[0][t] + wpart[1][t] + wpart[2][t] + wpart[3][t];
        atomicAdd(&g_stats[t], v);
    }
}

// ------------------------------------------------------------------
// K2: h1 = relu(bn1(u+vj)); packed stats of h1@W2+b2
__global__ __launch_bounds__(128) void k2_stats2(
    const float* __restrict__ pos,
    const float* __restrict__ w1, const float* __restrict__ b1,
    const float* __restrict__ g1, const float* __restrict__ be1,
    const float* __restrict__ w2, const float* __restrict__ b2)
{
    __shared__ float v1s[PP * 17];
    __shared__ float w1u[48], w1v[48], b1s[16];
    __shared__ __align__(16) float sw2[256];
    __shared__ __align__(16) float sb2[16];
    __shared__ float bn1s[16], bn1o[16];
    __shared__ float wpart[4][32];

    int b = blockIdx.x, t = threadIdx.x;
    float px = pos[(b * PP + t) * 3 + 0];
    float py = pos[(b * PP + t) * 3 + 1];
    float pz = pos[(b * PP + t) * 3 + 2];
    if (t < 48) { w1u[t] = w1[t] - w1[t + 48]; w1v[t] = w1[t + 48]; }
    if (t < 16) b1s[t] = b1[t];
    sw2[t] = w2[t]; sw2[t + 128] = w2[t + 128];
    if (t < 16) sb2[t] = b2[t];
    if (t >= 32 && t < 48) {
        int c = t - 32;
        const float N = (float)BG * PP * KN;
        float m = g_stats[c] / N;
        float v = g_stats[16 + c] / N - m * m;
        float sc = g1[c] * rsqrtf(v + EPSB);
        bn1s[c] = sc; bn1o[c] = be1[c] - m * sc;
    }
    __syncthreads();

    float u1[16];
#pragma unroll
    for (int c = 0; c < 16; ++c) {
        u1[c] = b1s[c] + px * w1u[c] + py * w1u[16 + c] + pz * w1u[32 + c];
        v1s[t * 17 + c] = px * w1v[c] + py * w1v[16 + c] + pz * w1v[32 + c];
    }
    __syncthreads();

    const unsigned* oi = g_idx1 + ((size_t)b * PP + t) * 5;
    const ulonglong2* sw2u2 = (const ulonglong2*)sw2;
    const u64* sb2u = (const u64*)sb2;

    u64 S[8], Q[8];
#pragma unroll
    for (int g = 0; g < 8; ++g) { S[g] = 0ull; Q[g] = 0ull; }
#pragma unroll 1
    for (int w = 0; w < 5; ++w) {
        unsigned pk = oi[w];
#pragma unroll 1
        for (int kk = 0; kk < 4; ++kk) {
            int j = (int)(pk & 255u); pk >>= 8;
            float h1[16];
#pragma unroll
            for (int c = 0; c < 16; ++c) {
                float pre = u1[c] + v1s[j * 17 + c];
                h1[c] = fmaxf(fmaf(pre, bn1s[c], bn1o[c]), 0.f);
            }
            u64 A2[8];
#pragma unroll
            for (int g = 0; g < 8; ++g) A2[g] = sb2u[g];
#pragma unroll
            for (int f = 0; f < 16; ++f) {
                u64 hv = pk2(h1[f], h1[f]);
                ulonglong2 w0 = sw2u2[f * 4 + 0], w1q = sw2u2[f * 4 + 1];
                ulonglong2 w2q = sw2u2[f * 4 + 2], w3q = sw2u2[f * 4 + 3];
                A2[0] = fma2(hv, w0.x, A2[0]);  A2[1] = fma2(hv, w0.y, A2[1]);
                A2[2] = fma2(hv, w1q.x, A2[2]); A2[3] = fma2(hv, w1q.y, A2[3]);
                A2[4] = fma2(hv, w2q.x, A2[4]); A2[5] = fma2(hv, w2q.y, A2[5]);
                A2[6] = fma2(hv, w3q.x, A2[6]); A2[7] = fma2(hv, w3q.y, A2[7]);
            }
#pragma unroll
            for (int g = 0; g < 8; ++g) {
                S[g] = add2(S[g], A2[g]);
                Q[g] = fma2(A2[g], A2[g], Q[g]);
            }
        }
    }
    float s[16], q[16];
#pragma unroll
    for (int g = 0; g < 8; ++g) {
        upk2(s[2 * g], s[2 * g + 1], S[g]);
        upk2(q[2 * g], q[2 * g + 1], Q[g]);
    }
#pragma unroll
    for (int c = 0; c < 16; ++c) {
        for (int o = 16; o > 0; o >>= 1) {
            s[c] += __shfl_xor_sync(0xffffffffu, s[c], o);
            q[c] += __shfl_xor_sync(0xffffffffu, q[c], o);
        }
    }
    int lane = t & 31, wid = t >> 5;
    if (lane == 0) {
#pragma unroll
        for (int c = 0; c < 16; ++c) { wpart[wid][c] = s[c]; wpart[wid][16 + c] = q[c]; }
    }
    __syncthreads();
    if (t < 32) {
        float v = wpart[0][t] + wpart[1][t] + wpart[2][t] + wpart[3][t];
        atomicAdd(&g_stats[32 + t], v);
    }
}

// ------------------------------------------------------------------
// K3: conv1 final -> x1 ; kNN2 (4 cand/iter, packed dots) ; conv2 ;
//     lin1 (unroll 4) ; head ; log_softmax
__global__ __launch_bounds__(128, 1) void k3_mega(
    const float* __restrict__ pos,
    const float* __restrict__ w1, const float* __restrict__ b1,
    const float* __restrict__ g1, const float* __restrict__ be1,
    const float* __restrict__ w2, const float* __restrict__ b2,
    const float* __restrict__ g2, const float* __restrict__ be2,
    const float* __restrict__ w3, const float* __restrict__ b3,
    const float* __restrict__ c2w, const float* __restrict__ c2b,
    const float* __restrict__ lw,  const float* __restrict__ lb,
    const float* __restrict__ mw1, const float* __restrict__ mb1,
    const float* __restrict__ mw2, const float* __restrict__ mb2,
    const float* __restrict__ mw3, const float* __restrict__ mb3,
    float* __restrict__ out)
{
    __shared__ __align__(16) float pool[6784];
    __shared__ float sn2[PP];
    __shared__ unsigned char nb2[PP * KN];
    __shared__ float w1u[48], w1v[48], b1s[16], bn1s[16], bn1o[16];
    __shared__ __align__(16) float sw2[256];
    __shared__ __align__(16) float sw3[256];
    __shared__ __align__(16) float sb2[16];
    __shared__ float sb3[16], bn2s[16], bn2o[16];
    __shared__ __align__(16) float c2u[512];
    __shared__ __align__(16) float c2v[512];
    __shared__ __align__(16) float c2bs[32];
    __shared__ float wm[128 * 4];
    __shared__ float gvec[128], h1s[64], h2s[64], outs[2];

    int b = blockIdx.x, t = threadIdx.x;
    int lane = t & 31, wid = t >> 5;
    float px = pos[(b * PP + t) * 3 + 0];
    float py = pos[(b * PP + t) * 3 + 1];
    float pz = pos[(b * PP + t) * 3 + 2];
    if (t < 48) { w1u[t] = w1[t] - w1[t + 48]; w1v[t] = w1[t + 48]; }
    if (t < 16) { b1s[t] = b1[t]; sb2[t] = b2[t]; sb3[t] = b3[t]; }
    sw2[t] = w2[t]; sw2[t + 128] = w2[t + 128];
    sw3[t] = w3[t]; sw3[t + 128] = w3[t + 128];
#pragma unroll
    for (int i = t; i < 512; i += 128) { c2u[i] = c2w[i] - c2w[i + 512]; c2v[i] = c2w[i + 512]; }
    if (t < 32) c2bs[t] = c2b[t];
    {
        const float N = (float)BG * PP * KN;
        if (t >= 64 && t < 80) {
            int c = t - 64;
            float m = g_stats[c] / N;
            float v = g_stats[16 + c] / N - m * m;
            float sc = g1[c] * rsqrtf(v + EPSB);
            bn1s[c] = sc; bn1o[c] = be1[c] - m * sc;
        } else if (t >= 80 && t < 96) {
            int c = t - 80;
            float m = g_stats[32 + c] / N;
            float v = g_stats[48 + c] / N - m * m;
            float sc = g2[c] * rsqrtf(v + EPSB);
            bn2s[c] = sc; bn2o[c] = be2[c] - m * sc;
        }
    }
    __syncthreads();   // all weights/bn consts ready; pool free

    // phase A: u1 (regs) + v1 rows (pool, stride 20, float4 writes)
    float u1[16];
    {
        float vv[16];
#pragma unroll
        for (int c = 0; c < 16; ++c) {
            u1[c] = b1s[c] + px * w1u[c] + py * w1u[16 + c] + pz * w1u[32 + c];
            vv[c] = px * w1v[c] + py * w1v[16 + c] + pz * w1v[32 + c];
        }
        float4* vr = (float4*)pool + t * 5;
#pragma unroll
        for (int g = 0; g < 4; ++g)
            vr[g] = make_float4(vv[4 * g], vv[4 * g + 1], vv[4 * g + 2], vv[4 * g + 3]);
    }
    __syncthreads();

    // ---- conv1 over 20 edges (packed f32x2 layers) ----
    const unsigned* oi = g_idx1 + ((size_t)b * PP + t) * 5;
    const ulonglong2* sw2u2 = (const ulonglong2*)sw2;
    const ulonglong2* sw3u2 = (const ulonglong2*)sw3;
    const u64* sb2u = (const u64*)sb2;
    float x1a[16];
#pragma unroll
    for (int c = 0; c < 16; ++c) x1a[c] = -1e30f;
#pragma unroll 1
    for (int w = 0; w < 5; ++w) {
        unsigned pk = oi[w];
#pragma unroll 1
        for (int kk = 0; kk < 4; ++kk) {
            int j = (int)(pk & 255u); pk >>= 8;
            const float4* vp = (const float4*)pool + j * 5;
            float4 q0 = vp[0], q1 = vp[1], q2 = vp[2], q3 = vp[3];
            float h1v[16];
            h1v[0]  = fmaxf(fmaf(u1[0]  + q0.x, bn1s[0],  bn1o[0]),  0.f);
            h1v[1]  = fmaxf(fmaf(u1[1]  + q0.y, bn1s[1],  bn1o[1]),  0.f);
            h1v[2]  = fmaxf(fmaf(u1[2]  + q0.z, bn1s[2],  bn1o[2]),  0.f);
            h1v[3]  = fmaxf(fmaf(u1[3]  + q0.w, bn1s[3],  bn1o[3]),  0.f);
            h1v[4]  = fmaxf(fmaf(u1[4]  + q1.x, bn1s[4],  bn1o[4]),  0.f);
            h1v[5]  = fmaxf(fmaf(u1[5]  + q1.y, bn1s[5],  bn1o[5]),  0.f);
            h1v[6]  = fmaxf(fmaf(u1[6]  + q1.z, bn1s[6],  bn1o[6]),  0.f);
            h1v[7]  = fmaxf(fmaf(u1[7]  + q1.w, bn1s[7],  bn1o[7]),  0.f);
            h1v[8]  = fmaxf(fmaf(u1[8]  + q2.x, bn1s[8],  bn1o[8]),  0.f);
            h1v[9]  = fmaxf(fmaf(u1[9]  + q2.y, bn1s[9],  bn1o[9]),  0.f);
            h1v[10] = fmaxf(fmaf(u1[10] + q2.z, bn1s[10], bn1o[10]), 0.f);
            h1v[11] = fmaxf(fmaf(u1[11] + q2.w, bn1s[11], bn1o[11]), 0.f);
            h1v[12] = fmaxf(fmaf(u1[12] + q3.x, bn1s[12], bn1o[12]), 0.f);
            h1v[13] = fmaxf(fmaf(u1[13] + q3.y, bn1s[13], bn1o[13]), 0.f);
            h1v[14] = fmaxf(fmaf(u1[14] + q3.z, bn1s[14], bn1o[14]), 0.f);
            h1v[15] = fmaxf(fmaf(u1[15] + q3.w, bn1s[15], bn1o[15]), 0.f);

            u64 A2[8];
#pragma unroll
            for (int g = 0; g < 8; ++g) A2[g] = sb2u[g];
#pragma unroll
            for (int f = 0; f < 16; ++f) {
                u64 hv = pk2(h1v[f], h1v[f]);
                ulonglong2 w0 = sw2u2[f * 4 + 0], w1q = sw2u2[f * 4 + 1];
                ulonglong2 w2q = sw2u2[f * 4 + 2], w3q = sw2u2[f * 4 + 3];
                A2[0] = fma2(hv, w0.x, A2[0]);  A2[1] = fma2(hv, w0.y, A2[1]);
                A2[2] = fma2(hv, w1q.x, A2[2]); A2[3] = fma2(hv, w1q.y, A2[3]);
                A2[4] = fma2(hv, w2q.x, A2[4]); A2[5] = fma2(hv, w2q.y, A2[5]);
                A2[6] = fma2(hv, w3q.x, A2[6]); A2[7] = fma2(hv, w3q.y, A2[7]);
            }
            float h2v[16];
#pragma unroll
            for (int g = 0; g < 8; ++g) {
                float a, bb; upk2(a, bb, A2[g]);
                h2v[2 * g]     = fmaxf(fmaf(a,  bn2s[2 * g],     bn2o[2 * g]),     0.f);
                h2v[2 * g + 1] = fmaxf(fmaf(bb, bn2s[2 * g + 1], bn2o[2 * g + 1]), 0.f);
            }
            u64 A3[8];
#pragma unroll
            for (int g = 0; g < 8; ++g) A3[g] = 0ull;
#pragma unroll
            for (int f = 0; f < 16; ++f) {
                u64 hv = pk2(h2v[f], h2v[f]);
                ulonglong2 w0 = sw3u2[f * 4 + 0], w1q = sw3u2[f * 4 + 1];
                ulonglong2 w2q = sw3u2[f * 4 + 2], w3q = sw3u2[f * 4 + 3];
                A3[0] = fma2(hv, w0.x, A3[0]);  A3[1] = fma2(hv, w0.y, A3[1]);
                A3[2] = fma2(hv, w1q.x, A3[2]); A3[3] = fma2(hv, w1q.y, A3[3]);
                A3[4] = fma2(hv, w2q.x, A3[4]); A3[5] = fma2(hv, w2q.y, A3[5]);
                A3[6] = fma2(hv, w3q.x, A3[6]); A3[7] = fma2(hv, w3q.y, A3[7]);
            }
#pragma unroll
            for (int g = 0; g < 8; ++g) {
                float a, bb; upk2(a, bb, A3[g]);
                x1a[2 * g]     = fmaxf(x1a[2 * g],     a);
                x1a[2 * g + 1] = fmaxf(x1a[2 * g + 1], bb);
            }
        }
    }
    float x1f[16];
    float n2 = 0.f;
#pragma unroll
    for (int c = 0; c < 16; ++c) { x1f[c] = x1a[c] + sb3[c]; n2 = fmaf(x1f[c], x1f[c], n2); }
    __syncthreads();   // all v1 reads done
    {
        float4* xr = (float4*)pool + t * 5;
#pragma unroll
        for (int g = 0; g < 4; ++g)
            xr[g] = make_float4(x1f[4 * g], x1f[4 * g + 1], x1f[4 * g + 2], x1f[4 * g + 3]);
        sn2[t] = n2;
    }
    __syncthreads();

    // ---- kNN2: 4 candidates/iter, packed f32x2 dots, 2 inserts per list ----
    u64 xq[8];
#pragma unroll
    for (int g = 0; g < 8; ++g) xq[g] = pk2(x1f[2 * g], x1f[2 * g + 1]);

    float kA[KN], kB[KN];
#pragma unroll
    for (int k = 0; k < KN; ++k) { kA[k] = 1e38f; kB[k] = 1e38f; }
#pragma unroll 1
    for (int j = 0; j < PP; j += 4) {
        float dd[4];
#pragma unroll
        for (int s = 0; s < 4; ++s) {
            const ulonglong2* rp = (const ulonglong2*)(pool + (j + s) * 20);
            ulonglong2 r0 = rp[0], r1 = rp[1], r2 = rp[2], r3 = rp[3];
            u64 a0 = 0ull, a1 = 0ull;
            a0 = fma2(xq[0], r0.x, a0); a1 = fma2(xq[1], r0.y, a1);
            a0 = fma2(xq[2], r1.x, a0); a1 = fma2(xq[3], r1.y, a1);
            a0 = fma2(xq[4], r2.x, a0); a1 = fma2(xq[5], r2.y, a1);
            a0 = fma2(xq[6], r3.x, a0); a1 = fma2(xq[7], r3.y, a1);
            float l0, h0, l1, h1; upk2(l0, h0, a0); upk2(l1, h1, a1);
            float dot = (l0 + h0) + (l1 + h1);
            dd[s] = n2 + sn2[j + s] - 2.f * dot;
        }
        if (j == t)     dd[0] = 1e30f;
        if (j + 1 == t) dd[1] = 1e30f;
        if (j + 2 == t) dd[2] = 1e30f;
        if (j + 3 == t) dd[3] = 1e30f;
        ins20(kA, embed(dd[0], j));
        ins20(kA, embed(dd[2], j + 2));
        ins20(kB, embed(dd[1], j + 1));
        ins20(kB, embed(dd[3], j + 3));
    }
#pragma unroll
    for (int k = 0; k < KN; ++k)
        nb2[t * KN + k] = (unsigned char)(__float_as_uint(fminf(kA[k], kB[KN - 1 - k])) & 127u);

    // ---- conv2: v2 = x1f@Wv -> smem (stride 33); x2 = u2 + max_k v2[j] ----
    float* v2s = pool + 2560;
    {
        const ulonglong2* cv = (const ulonglong2*)c2v;
        u64 V[16];
#pragma unroll
        for (int g = 0; g < 16; ++g) V[g] = 0ull;
#pragma unroll
        for (int f = 0; f < 16; ++f) {
            u64 hv = pk2(x1f[f], x1f[f]);
#pragma unroll
            for (int g = 0; g < 8; ++g) {
                ulonglong2 wv = cv[f * 8 + g];
                V[2 * g]     = fma2(hv, wv.x, V[2 * g]);
                V[2 * g + 1] = fma2(hv, wv.y, V[2 * g + 1]);
            }
        }
#pragma unroll
        for (int g = 0; g < 16; ++g) {
            float a, bb; upk2(a, bb, V[g]);
            v2s[t * 33 + 2 * g] = a; v2s[t * 33 + 2 * g + 1] = bb;
        }
    }
    __syncthreads();

    float x2m[32];
#pragma unroll
    for (int c = 0; c < 32; ++c) x2m[c] = -1e30f;
#pragma unroll 1
    for (int k = 0; k < KN; ++k) {
        int j = (int)nb2[t * KN + k];
#pragma unroll
        for (int c = 0; c < 32; ++c) x2m[c] = fmaxf(x2m[c], v2s[j * 33 + c]);
    }
    float x2a[32];
    {
        const ulonglong2* cu = (const ulonglong2*)c2u;
        const u64* cbu = (const u64*)c2bs;
        u64 U[16];
#pragma unroll
        for (int g = 0; g < 16; ++g) U[g] = cbu[g];
#pragma unroll
        for (int f = 0; f < 16; ++f) {
            u64 hv = pk2(x1f[f], x1f[f]);
#pragma unroll
            for (int g = 0; g < 8; ++g) {
                ulonglong2 wv = cu[f * 8 + g];
                U[2 * g]     = fma2(hv, wv.x, U[2 * g]);
                U[2 * g + 1] = fma2(hv, wv.y, U[2 * g + 1]);
            }
        }
#pragma unroll
        for (int g = 0; g < 16; ++g) {
            float a, bb; upk2(a, bb, U[g]);
            x2a[2 * g]     = a  + x2m[2 * g];
            x2a[2 * g + 1] = bb + x2m[2 * g + 1];
        }
    }
    __syncthreads();   // all v2/x1s reads done; pool free

    // ---- load lin1 weights transposed: lwt[c][f] = lw[f][c] (pool 0..6144) ----
#pragma unroll 1
    for (int i = t; i < 48 * 128; i += 128) {
        int c = i / 48, f = i - c * 48;
        pool[i] = lw[f * 128 + c];
    }
    __syncthreads();

    // ---- lin1: per-channel broadcast dot (packed) + shuffle/cross-warp max,
    //      4 channels in flight to hide shuffle latency ----
    u64 F2[24];
#pragma unroll
    for (int g = 0; g < 8; ++g)  F2[g]     = pk2(x1f[2 * g], x1f[2 * g + 1]);
#pragma unroll
    for (int g = 0; g < 16; ++g) F2[8 + g] = pk2(x2a[2 * g], x2a[2 * g + 1]);
#pragma unroll 4
    for (int c = 0; c < 128; ++c) {
        const ulonglong2* rw = (const ulonglong2*)(pool + c * 48);
        u64 a0 = 0ull, a1 = 0ull;
#pragma unroll
        for (int g = 0; g < 12; ++g) {
            ulonglong2 wv = rw[g];
            a0 = fma2(F2[2 * g],     wv.x, a0);
            a1 = fma2(F2[2 * g + 1], wv.y, a1);
        }
        float lo, hi; upk2(lo, hi, add2(a0, a1));
        float v = lo + hi;
#pragma unroll
        for (int o = 16; o > 0; o >>= 1)
            v = fmaxf(v, __shfl_xor_sync(0xffffffffu, v, o));
        if (lane == 0) wm[c * 4 + wid] = v;
    }
    __syncthreads();
    gvec[t] = fmaxf(fmaxf(wm[t * 4 + 0], wm[t * 4 + 1]),
                    fmaxf(wm[t * 4 + 2], wm[t * 4 + 3])) + __ldg(lb + t);
    __syncthreads();

    // ---- head MLP 128->64->64->2 + log_softmax ----
    if (t < 64) {
        float a = mb1[t];
#pragma unroll 4
        for (int i = 0; i < 128; ++i) a = fmaf(gvec[i], mw1[i * 64 + t], a);
        h1s[t] = fmaxf(a, 0.f);
    }
    __syncthreads();
    if (t < 64) {
        float a = mb2[t];
#pragma unroll 4
        for (int i = 0; i < 64; ++i) a = fmaf(h1s[i], mw2[i * 64 + t], a);
        h2s[t] = fmaxf(a, 0.f);
    }
    __syncthreads();
    if (t < 2) {
        float a = mb3[t];
#pragma unroll 4
        for (int i = 0; i < 64; ++i) a = fmaf(h2s[i], mw3[i * 2 + t], a);
        outs[t] = a;
    }
    __syncthreads();
    if (t == 0) {
        float o0 = outs[0], o1 = outs[1];
        float m = fmaxf(o0, o1);
        float lse = m + logf(expf(o0 - m) + expf(o1 - m));
        out[b * 2 + 0] = o0 - lse;
        out[b * 2 + 1] = o1 - lse;
    }
}

// ------------------------------------------------------------------
extern "C" void kernel_launch(void* const* d_in, const int* in_sizes, int n_in,
                              void* d_out, int out_size)
{
    (void)in_sizes; (void)n_in; (void)out_size;
    const float* pos   = (const float*)d_in[0];
    const float* c1_w1 = (const float*)d_in[2];
    const float* c1_b1 = (const float*)d_in[3];
    const float* c1_g1 = (const float*)d_in[4];
    const float* c1_be1= (const float*)d_in[5];
    const float* c1_w2 = (const float*)d_in[6];
    const float* c1_b2 = (const float*)d_in[7];
    const float* c1_g2 = (const float*)d_in[8];
    const float* c1_be2= (const float*)d_in[9];
    const float* c1_w3 = (const float*)d_in[10];
    const float* c1_b3 = (const float*)d_in[11];
    const float* c2_w  = (const float*)d_in[12];
    const float* c2_b  = (const float*)d_in[13];
    const float* lw    = (const float*)d_in[14];
    const float* lb    = (const float*)d_in[15];
    const float* m_w1  = (const float*)d_in[16];
    const float* m_b1  = (const float*)d_in[17];
    const float* m_w2  = (const float*)d_in[18];
    const float* m_b2  = (const float*)d_in[19];
    const float* m_w3  = (const float*)d_in[20];
    const float* m_b3  = (const float*)d_in[21];
    float* out = (float*)d_out;

    k0_zero<<<1, 64>>>();
    k1_knn_stats<<<BG, 128>>>(pos, c1_w1, c1_b1);
    k2_stats2<<<BG, 128>>>(pos, c1_w1, c1_b1, c1_g1, c1_be1, c1_w2, c1_b2);
    k3_mega<<<BG, 128>>>(pos,
                         c1_w1, c1_b1, c1_g1, c1_be1,
                         c1_w2, c1_b2, c1_g2, c1_be2,
                         c1_w3, c1_b3,
                         c2_w, c2_b, lw, lb,
                         m_w1, m_b1, m_w2, m_b2, m_w3, m_b3,
                         out);
}